// round 9
// baseline (speedup 1.0000x reference)
#include <cuda_runtime.h>
#include <cuda_bf16.h>
#include <cstdint>

#define N_NODES 50000
#define N_EDGES 800000
#define C_HID   512
#define C_OUT   256
#define WSZ     (C_HID * C_HID)

// ------------------------- scratch (device globals; no allocation) ----------
__device__ __align__(256) int   g_cnt[N_NODES];
__device__ __align__(256) int   g_rowstart[N_NODES + 1];
__device__ __align__(256) int   g_cursor[N_NODES];
__device__ __align__(256) float g_dinv[N_NODES];
__device__ __align__(256) int   g_csr_src[N_EDGES];
__device__ __align__(256) float g_csr_w[N_EDGES];
__device__ __align__(256) float g_H[(size_t)N_NODES * C_HID];
__device__ __align__(256) float g_G[(size_t)N_NODES * C_HID];
__device__ __align__(256) __nv_bfloat16 g_Ah[(size_t)N_NODES * C_HID];
__device__ __align__(256) __nv_bfloat16 g_Al[(size_t)N_NODES * C_HID];
__device__ __align__(256) __nv_bfloat16 g_Wh[3][WSZ];
__device__ __align__(256) __nv_bfloat16 g_Wl[3][WSZ];
__device__ int g_is64;   // 1 if edge_index is int64, 0 if int32

// ------------------------- small helpers ------------------------------------
__device__ __forceinline__ uint32_t smem_u32(const void* p) {
    return (uint32_t)__cvta_generic_to_shared(p);
}

__device__ __forceinline__ void cp_async16(uint32_t saddr, const void* gptr, int src_size) {
    asm volatile("cp.async.cg.shared.global [%0], [%1], 16, %2;\n"
                 :: "r"(saddr), "l"(gptr), "r"(src_size));
}

__device__ __forceinline__ void mma_16816(float* c, const uint32_t* a, const uint32_t* b) {
    asm volatile(
        "mma.sync.aligned.m16n8k16.row.col.f32.bf16.bf16.f32 "
        "{%0,%1,%2,%3},{%4,%5,%6,%7},{%8,%9},{%0,%1,%2,%3};"
        : "+f"(c[0]), "+f"(c[1]), "+f"(c[2]), "+f"(c[3])
        : "r"(a[0]), "r"(a[1]), "r"(a[2]), "r"(a[3]), "r"(b[0]), "r"(b[1]));
}

// Load edge index element `pos` honoring runtime dtype flag.
__device__ __forceinline__ int load_idx(const void* ei, long long pos, int is64) {
    if (is64) return (int)((const long long*)ei)[pos];
    return ((const int*)ei)[pos];
}

// ------------------------- graph preprocessing kernels ----------------------
// Detect int32 vs int64 edge_index: for little-endian int64 values < 2^32,
// every odd int32 word is zero. Random int32 node ids make that astronomically
// unlikely over 256 samples.
__global__ void detect_kernel(const int* __restrict__ ei32) {
    if (threadIdx.x == 0) {
        int is64 = 1;
        for (int k = 1; k < 512; k += 2)
            if (ei32[k] != 0) { is64 = 0; break; }
        g_is64 = is64;
    }
}

__global__ void zero_kernel() {
    int i = blockIdx.x * blockDim.x + threadIdx.x;
    if (i < N_NODES) { g_cnt[i] = 0; g_cursor[i] = 0; }
}

__global__ void deg_kernel(const void* __restrict__ ei) {
    int e = blockIdx.x * blockDim.x + threadIdx.x;
    if (e >= N_EDGES) return;
    int is64 = g_is64;
    int d = load_idx(ei, (long long)N_EDGES + e, is64);
    atomicAdd(&g_cnt[d], 1);
}

__global__ void dinv_kernel() {
    int i = blockIdx.x * blockDim.x + threadIdx.x;
    if (i < N_NODES) g_dinv[i] = rsqrtf((float)(g_cnt[i] + 1));  // +1 self-loop
}

// single-block exclusive scan of g_cnt -> g_rowstart (50001 entries)
__global__ void scan_kernel() {
    __shared__ int s[1024];
    const int CHK = (N_NODES + 1023) / 1024;  // 49
    int t = threadIdx.x;
    int base = t * CHK;
    int sum = 0;
    for (int j = 0; j < CHK; j++) {
        int i = base + j;
        if (i < N_NODES) sum += g_cnt[i];
    }
    s[t] = sum;
    __syncthreads();
    for (int off = 1; off < 1024; off <<= 1) {
        int v = (t >= off) ? s[t - off] : 0;
        __syncthreads();
        s[t] += v;
        __syncthreads();
    }
    int run = (t == 0) ? 0 : s[t - 1];
    for (int j = 0; j < CHK; j++) {
        int i = base + j;
        if (i < N_NODES) { g_rowstart[i] = run; run += g_cnt[i]; }
    }
    if (t == 1023) g_rowstart[N_NODES] = run;
}

__global__ void scatter_kernel(const void* __restrict__ ei) {
    int e = blockIdx.x * blockDim.x + threadIdx.x;
    if (e >= N_EDGES) return;
    int is64 = g_is64;
    int s = load_idx(ei, e, is64);
    int d = load_idx(ei, (long long)N_EDGES + e, is64);
    int pos = g_rowstart[d] + atomicAdd(&g_cursor[d], 1);
    g_csr_src[pos] = s;
    g_csr_w[pos]   = g_dinv[s] * g_dinv[d];
}

// ------------------------- fp32 -> bf16 hi/lo split -------------------------
__global__ void split_kernel(const float* __restrict__ x,
                             __nv_bfloat16* __restrict__ hi,
                             __nv_bfloat16* __restrict__ lo, int n) {
    int i = blockIdx.x * blockDim.x + threadIdx.x;
    if (i >= n) return;
    float v = x[i];
    __nv_bfloat16 h = __float2bfloat16(v);
    float r = v - __bfloat162float(h);
    hi[i] = h;
    lo[i] = __float2bfloat16(r);
}

// ------------------------- GEMM: C = Ah*Bh + Al*Bh + Ah*Bl ------------------
// A: [M, 512] row-major bf16 (hi/lo); B: [512, N] row-major bf16 (hi/lo); C fp32.
// Block tile 128x128, ktile 32, 8 warps (2x4), warp tile 64x32, double-buffered
// cp.async pipeline, ldmatrix + mma.sync m16n8k16.
__global__ __launch_bounds__(256) void gemm_bf16x3(
    const __nv_bfloat16* __restrict__ Ah, const __nv_bfloat16* __restrict__ Al,
    const __nv_bfloat16* __restrict__ Bh, const __nv_bfloat16* __restrict__ Bl,
    float* __restrict__ C, int M, int N)
{
    __shared__ __align__(16) __nv_bfloat16 As[2][128 * 40];
    __shared__ __align__(16) __nv_bfloat16 Bs[2][32 * 136];

    const int tid  = threadIdx.x;
    const int lane = tid & 31;
    const int w    = tid >> 5;
    const int wr   = w >> 2;   // 0..1
    const int wc   = w & 3;    // 0..3
    const int m0   = blockIdx.x * 128;
    const int n0   = blockIdx.y * 128;

    float acc[4][4][4];
#pragma unroll
    for (int a = 0; a < 4; a++)
#pragma unroll
        for (int b = 0; b < 4; b++)
#pragma unroll
            for (int cc = 0; cc < 4; cc++) acc[a][b][cc] = 0.f;

    const int NIT = 48;  // 3 segments * 16 k-tiles of 32

    auto loadstage = [&](int it, int st) {
        int seg = it >> 4;
        int k0  = (it & 15) << 5;
        const __nv_bfloat16* A = (seg == 1) ? Al : Ah;
        const __nv_bfloat16* B = (seg == 2) ? Bl : Bh;
#pragma unroll
        for (int r = 0; r < 2; r++) {           // A tile: 128x32
            int s   = tid + r * 256;
            int row = s >> 2;
            int c4  = s & 3;
            int gr  = m0 + row;
            int sz  = (gr < M) ? 16 : 0;
            int grc = (gr < M) ? gr : (M - 1);
            const __nv_bfloat16* gp = A + (size_t)grc * 512 + k0 + c4 * 8;
            cp_async16(smem_u32(&As[st][row * 40 + c4 * 8]), gp, sz);
        }
#pragma unroll
        for (int r = 0; r < 2; r++) {           // B tile: 32x128
            int s   = tid + r * 256;
            int row = s >> 4;
            int cc  = (s & 15) * 8;
            const __nv_bfloat16* gp = B + (size_t)(k0 + row) * N + n0 + cc;
            cp_async16(smem_u32(&Bs[st][row * 136 + cc]), gp, 16);
        }
        asm volatile("cp.async.commit_group;\n" ::);
    };

    loadstage(0, 0);
    for (int it = 0; it < NIT; it++) {
        int st = it & 1;
        if (it + 1 < NIT) {
            loadstage(it + 1, st ^ 1);
            asm volatile("cp.async.wait_group 1;\n" ::);
        } else {
            asm volatile("cp.async.wait_group 0;\n" ::);
        }
        __syncthreads();

#pragma unroll
        for (int ks = 0; ks < 2; ks++) {
            int kk = ks * 16;
            uint32_t afr[4][4];
            int lr = lane & 15;
            int lc = (lane >> 4) * 8;
#pragma unroll
            for (int mt = 0; mt < 4; mt++) {
                uint32_t addr = smem_u32(&As[st][(wr * 64 + mt * 16 + lr) * 40 + kk + lc]);
                asm volatile("ldmatrix.sync.aligned.m8n8.x4.shared.b16 {%0,%1,%2,%3},[%4];"
                             : "=r"(afr[mt][0]), "=r"(afr[mt][1]),
                               "=r"(afr[mt][2]), "=r"(afr[mt][3])
                             : "r"(addr));
            }
            uint32_t bfr[4][2];
#pragma unroll
            for (int np = 0; np < 2; np++) {
                int krow = kk + (lane & 7) + ((lane >> 3) & 1) * 8;
                int col  = wc * 32 + np * 16 + ((lane >> 4) & 1) * 8;
                uint32_t addr = smem_u32(&Bs[st][krow * 136 + col]);
                uint32_t r0, r1, r2, r3;
                asm volatile("ldmatrix.sync.aligned.m8n8.x4.trans.shared.b16 {%0,%1,%2,%3},[%4];"
                             : "=r"(r0), "=r"(r1), "=r"(r2), "=r"(r3)
                             : "r"(addr));
                bfr[np * 2][0] = r0; bfr[np * 2][1] = r1;
                bfr[np * 2 + 1][0] = r2; bfr[np * 2 + 1][1] = r3;
            }
#pragma unroll
            for (int mt = 0; mt < 4; mt++)
#pragma unroll
                for (int nt = 0; nt < 4; nt++)
                    mma_16816(acc[mt][nt], afr[mt], bfr[nt]);
        }
        __syncthreads();
    }

    // epilogue
    int g  = lane >> 2;
    int tq = lane & 3;
#pragma unroll
    for (int mt = 0; mt < 4; mt++) {
#pragma unroll
        for (int nt = 0; nt < 4; nt++) {
            int row = m0 + wr * 64 + mt * 16 + g;
            int col = n0 + wc * 32 + nt * 8 + tq * 2;
            if (row < M) {
                C[(size_t)row * N + col]     = acc[mt][nt][0];
                C[(size_t)row * N + col + 1] = acc[mt][nt][1];
            }
            if (row + 8 < M) {
                C[(size_t)(row + 8) * N + col]     = acc[mt][nt][2];
                C[(size_t)(row + 8) * N + col + 1] = acc[mt][nt][3];
            }
        }
    }
}

// ------------------------- propagation (gather-CSR, no atomics) -------------
// out[i,:] = sum_e w_e * G[src_e,:] + dinv[i]^2 * G[i,:]  (+bias) (relu) (+res)
// one block per dst node, 128 threads, V channels per thread.
template <int CH, bool RELU, bool RES>
__global__ void prop_kernel(const float* __restrict__ G,
                            const float* __restrict__ bias,
                            float* __restrict__ out) {
    constexpr int V = CH / 128;  // 4 (CH=512) or 2 (CH=256)
    __shared__ int   s_src[128];
    __shared__ float s_w[128];

    int i = blockIdx.x;
    int t = threadIdx.x;
    int c = t * V;

    float di = g_dinv[i];
    float sw = di * di;
    float acc[V];
    const float* gi = G + (size_t)i * CH + c;
    if constexpr (V == 4) {
        float4 v = *(const float4*)gi;
        acc[0] = sw * v.x; acc[1] = sw * v.y; acc[2] = sw * v.z; acc[3] = sw * v.w;
    } else {
        float2 v = *(const float2*)gi;
        acc[0] = sw * v.x; acc[1] = sw * v.y;
    }

    int beg = g_rowstart[i];
    int end = g_rowstart[i + 1];
    for (int e0 = beg; e0 < end; e0 += 128) {
        int n = end - e0;
        if (n > 128) n = 128;
        __syncthreads();
        if (t < n) {
            s_src[t] = g_csr_src[e0 + t];
            s_w[t]   = g_csr_w[e0 + t];
        }
        __syncthreads();
        for (int j = 0; j < n; j++) {
            float wv = s_w[j];
            const float* r = G + (size_t)s_src[j] * CH + c;
            if constexpr (V == 4) {
                float4 v = *(const float4*)r;
                acc[0] += wv * v.x; acc[1] += wv * v.y;
                acc[2] += wv * v.z; acc[3] += wv * v.w;
            } else {
                float2 v = *(const float2*)r;
                acc[0] += wv * v.x; acc[1] += wv * v.y;
            }
        }
    }

    float* o = out + (size_t)i * CH + c;
#pragma unroll
    for (int j = 0; j < V; j++) {
        float v = acc[j] + bias[c + j];
        if (RELU) v = v > 0.f ? v : 0.f;
        if (RES) v += o[j];  // out aliases H: read old value before overwrite
        o[j] = v;
    }
}

// ------------------------- driver -------------------------------------------
extern "C" void kernel_launch(void* const* d_in, const int* in_sizes, int n_in,
                              void* d_out, int out_size) {
    (void)in_sizes; (void)n_in; (void)out_size;
    const float* x   = (const float*)d_in[0];
    const void*  ei  = d_in[1];                 // int32 or int64, detected on device
    const float* W1  = (const float*)d_in[2];
    const float* b1  = (const float*)d_in[3];
    const float* Wr  = (const float*)d_in[4];
    const float* br  = (const float*)d_in[5];
    const float* Wx  = (const float*)d_in[6];
    const float* bx  = (const float*)d_in[7];
    float*       out = (float*)d_out;

    void* p;
    cudaGetSymbolAddress(&p, g_H);  float* H = (float*)p;
    cudaGetSymbolAddress(&p, g_G);  float* G = (float*)p;
    cudaGetSymbolAddress(&p, g_Ah); __nv_bfloat16* Ah = (__nv_bfloat16*)p;
    cudaGetSymbolAddress(&p, g_Al); __nv_bfloat16* Al = (__nv_bfloat16*)p;
    cudaGetSymbolAddress(&p, g_Wh); __nv_bfloat16* Wh = (__nv_bfloat16*)p;
    cudaGetSymbolAddress(&p, g_Wl); __nv_bfloat16* Wl = (__nv_bfloat16*)p;

    // graph preprocessing
    detect_kernel<<<1, 32>>>((const int*)ei);
    zero_kernel<<<(N_NODES + 255) / 256, 256>>>();
    deg_kernel<<<(N_EDGES + 255) / 256, 256>>>(ei);
    dinv_kernel<<<(N_NODES + 255) / 256, 256>>>();
    scan_kernel<<<1, 1024>>>();
    scatter_kernel<<<(N_EDGES + 255) / 256, 256>>>(ei);

    // weight splits (tiny)
    split_kernel<<<(WSZ + 255) / 256, 256>>>(W1, Wh + 0 * WSZ, Wl + 0 * WSZ, WSZ);
    split_kernel<<<(WSZ + 255) / 256, 256>>>(Wr, Wh + 1 * WSZ, Wl + 1 * WSZ, WSZ);
    split_kernel<<<(C_HID * C_OUT + 255) / 256, 256>>>(Wx, Wh + 2 * WSZ, Wl + 2 * WSZ,
                                                       C_HID * C_OUT);

    const int NE = N_NODES * C_HID;
    dim3 gg((N_NODES + 127) / 128, C_HID / 128);

    // layer 1: h = relu(P(x@W1) + b1)
    split_kernel<<<(NE + 255) / 256, 256>>>(x, Ah, Al, NE);
    gemm_bf16x3<<<gg, 256>>>(Ah, Al, Wh + 0 * WSZ, Wl + 0 * WSZ, G, N_NODES, C_HID);
    prop_kernel<512, true, false><<<N_NODES, 128>>>(G, b1, H);

    // 4 shared residual layers: h = relu(P(h@Wr) + br) + h
    for (int d = 0; d < 4; d++) {
        split_kernel<<<(NE + 255) / 256, 256>>>(H, Ah, Al, NE);
        gemm_bf16x3<<<gg, 256>>>(Ah, Al, Wh + 1 * WSZ, Wl + 1 * WSZ, G, N_NODES, C_HID);
        prop_kernel<512, true, true><<<N_NODES, 128>>>(G, br, H);
    }

    // output layer: out = P(h@Wx) + bx
    split_kernel<<<(NE + 255) / 256, 256>>>(H, Ah, Al, NE);
    dim3 g2((N_NODES + 127) / 128, C_OUT / 128);
    gemm_bf16x3<<<g2, 256>>>(Ah, Al, Wh + 2 * WSZ, Wl + 2 * WSZ, G, N_NODES, C_OUT);
    prop_kernel<256, false, false><<<N_NODES, 128>>>(G, bx, out);
}

// round 11
// speedup vs baseline: 1.1085x; 1.1085x over previous
#include <cuda_runtime.h>
#include <cuda_bf16.h>
#include <cstdint>

#define N_NODES 50000
#define N_EDGES 800000
#define C_HID   512
#define C_OUT   256
#define WSZ     (C_HID * C_HID)

// ------------------------- scratch (device globals; no allocation) ----------
__device__ __align__(256) int   g_cnt[N_NODES];
__device__ __align__(256) int   g_rowstart[N_NODES + 1];
__device__ __align__(256) int   g_cursor[N_NODES];
__device__ __align__(256) float g_dinv[N_NODES];
__device__ __align__(256) int   g_csr_src[N_EDGES];
__device__ __align__(256) float g_csr_w[N_EDGES];
__device__ __align__(256) float g_H[(size_t)N_NODES * C_HID];
__device__ __align__(256) float g_G[(size_t)N_NODES * C_HID];
__device__ __align__(256) __nv_bfloat16 g_Ah[(size_t)N_NODES * C_HID];
__device__ __align__(256) __nv_bfloat16 g_Al[(size_t)N_NODES * C_HID];
__device__ __align__(256) __nv_bfloat16 g_Wh[3][WSZ];   // [K,N] row-major
__device__ __align__(256) __nv_bfloat16 g_Wl[3][WSZ];
__device__ int g_is64;

// ------------------------- small helpers ------------------------------------
__device__ __forceinline__ uint32_t smem_u32(const void* p) {
    return (uint32_t)__cvta_generic_to_shared(p);
}

__device__ __forceinline__ void cp_async16(uint32_t saddr, const void* gptr, int src_size) {
    asm volatile("cp.async.cg.shared.global [%0], [%1], 16, %2;\n"
                 :: "r"(saddr), "l"(gptr), "r"(src_size));
}

__device__ __forceinline__ void mma_16816(float* c, const uint32_t* a, const uint32_t* b) {
    asm volatile(
        "mma.sync.aligned.m16n8k16.row.col.f32.bf16.bf16.f32 "
        "{%0,%1,%2,%3},{%4,%5,%6,%7},{%8,%9},{%0,%1,%2,%3};"
        : "+f"(c[0]), "+f"(c[1]), "+f"(c[2]), "+f"(c[3])
        : "r"(a[0]), "r"(a[1]), "r"(a[2]), "r"(a[3]), "r"(b[0]), "r"(b[1]));
}

__device__ __forceinline__ int load_idx(const void* ei, long long pos, int is64) {
    if (is64) return (int)((const long long*)ei)[pos];
    return ((const int*)ei)[pos];
}

// ------------------------- graph preprocessing kernels ----------------------
__global__ void detect_kernel(const int* __restrict__ ei32) {
    if (threadIdx.x == 0) {
        int is64 = 1;
        for (int k = 1; k < 512; k += 2)
            if (ei32[k] != 0) { is64 = 0; break; }
        g_is64 = is64;
    }
}

__global__ void zero_kernel() {
    int i = blockIdx.x * blockDim.x + threadIdx.x;
    if (i < N_NODES) { g_cnt[i] = 0; g_cursor[i] = 0; }
}

__global__ void deg_kernel(const void* __restrict__ ei) {
    int e = blockIdx.x * blockDim.x + threadIdx.x;
    if (e >= N_EDGES) return;
    int is64 = g_is64;
    int d = load_idx(ei, (long long)N_EDGES + e, is64);
    atomicAdd(&g_cnt[d], 1);
}

__global__ void dinv_kernel() {
    int i = blockIdx.x * blockDim.x + threadIdx.x;
    if (i < N_NODES) g_dinv[i] = rsqrtf((float)(g_cnt[i] + 1));
}

__global__ void scan_kernel() {
    __shared__ int s[1024];
    const int CHK = (N_NODES + 1023) / 1024;
    int t = threadIdx.x;
    int base = t * CHK;
    int sum = 0;
    for (int j = 0; j < CHK; j++) {
        int i = base + j;
        if (i < N_NODES) sum += g_cnt[i];
    }
    s[t] = sum;
    __syncthreads();
    for (int off = 1; off < 1024; off <<= 1) {
        int v = (t >= off) ? s[t - off] : 0;
        __syncthreads();
        s[t] += v;
        __syncthreads();
    }
    int run = (t == 0) ? 0 : s[t - 1];
    for (int j = 0; j < CHK; j++) {
        int i = base + j;
        if (i < N_NODES) { g_rowstart[i] = run; run += g_cnt[i]; }
    }
    if (t == 1023) g_rowstart[N_NODES] = run;
}

__global__ void scatter_kernel(const void* __restrict__ ei) {
    int e = blockIdx.x * blockDim.x + threadIdx.x;
    if (e >= N_EDGES) return;
    int is64 = g_is64;
    int s = load_idx(ei, e, is64);
    int d = load_idx(ei, (long long)N_EDGES + e, is64);
    int pos = g_rowstart[d] + atomicAdd(&g_cursor[d], 1);
    g_csr_src[pos] = s;
    g_csr_w[pos]   = g_dinv[s] * g_dinv[d];
}

// ------------------------- fp32 -> bf16 hi/lo split --------------------------
__global__ void split_kernel(const float* __restrict__ x,
                             __nv_bfloat16* __restrict__ hi,
                             __nv_bfloat16* __restrict__ lo, int n) {
    int i = blockIdx.x * blockDim.x + threadIdx.x;
    if (i >= n) return;
    float v = x[i];
    __nv_bfloat16 h = __float2bfloat16(v);
    hi[i] = h;
    lo[i] = __float2bfloat16(v - __bfloat162float(h));
}

// ------------------------- fused GEMM: C = Ah*Bh + Al*Bh + Ah*Bl ------------
// Single K-pass: per 32-k-tile load Ah,Al (128x32 each) and Bh,Bl (32x128
// each) once, issue all 3 mma combinations. Block tile 128x128, 8 warps
// (2x4), warp tile 64x32, double-buffered cp.async; dynamic smem 74KB.
#define AS_STRIDE 40
#define BS_STRIDE 136
#define AS_TILE (128 * AS_STRIDE)   // elems per A mat tile
#define BS_TILE (32 * BS_STRIDE)
#define GEMM_SMEM ((2 * 2 * AS_TILE + 2 * 2 * BS_TILE) * 2)  // bytes = 75776

__global__ __launch_bounds__(256) void gemm_bf16x3(
    const __nv_bfloat16* __restrict__ Ah, const __nv_bfloat16* __restrict__ Al,
    const __nv_bfloat16* __restrict__ Bh, const __nv_bfloat16* __restrict__ Bl,
    float* __restrict__ C, int M, int N)
{
    extern __shared__ __align__(16) __nv_bfloat16 sm[];
    __nv_bfloat16* As = sm;                       // [st][mat][128*40]
    __nv_bfloat16* Bs = sm + 2 * 2 * AS_TILE;     // [st][mat][32*136]

    const int tid  = threadIdx.x;
    const int lane = tid & 31;
    const int w    = tid >> 5;
    const int wr   = w >> 2;   // 0..1
    const int wc   = w & 3;    // 0..3
    const int m0   = blockIdx.x * 128;
    const int n0   = blockIdx.y * 128;

    float acc[4][4][4];
#pragma unroll
    for (int a = 0; a < 4; a++)
#pragma unroll
        for (int b = 0; b < 4; b++)
#pragma unroll
            for (int cc = 0; cc < 4; cc++) acc[a][b][cc] = 0.f;

    const int NIT = 16;  // K=512 / 32

    auto loadstage = [&](int it, int st) {
        int k0 = it << 5;
#pragma unroll
        for (int mat = 0; mat < 2; mat++) {
            const __nv_bfloat16* A = mat ? Al : Ah;
            __nv_bfloat16* dstA = As + (st * 2 + mat) * AS_TILE;
#pragma unroll
            for (int r = 0; r < 2; r++) {        // A tile: 128x32
                int s   = tid + r * 256;
                int row = s >> 2;
                int c4  = s & 3;
                int gr  = m0 + row;
                int sz  = (gr < M) ? 16 : 0;
                int grc = (gr < M) ? gr : (M - 1);
                const __nv_bfloat16* gp = A + (size_t)grc * 512 + k0 + c4 * 8;
                cp_async16(smem_u32(dstA + row * AS_STRIDE + c4 * 8), gp, sz);
            }
        }
#pragma unroll
        for (int mat = 0; mat < 2; mat++) {
            const __nv_bfloat16* B = mat ? Bl : Bh;
            __nv_bfloat16* dstB = Bs + (st * 2 + mat) * BS_TILE;
#pragma unroll
            for (int r = 0; r < 2; r++) {        // B tile: 32x128
                int s   = tid + r * 256;
                int row = s >> 4;
                int cc  = (s & 15) * 8;
                const __nv_bfloat16* gp = B + (size_t)(k0 + row) * N + n0 + cc;
                cp_async16(smem_u32(dstB + row * BS_STRIDE + cc), gp, 16);
            }
        }
        asm volatile("cp.async.commit_group;\n" ::);
    };

    loadstage(0, 0);
    for (int it = 0; it < NIT; it++) {
        int st = it & 1;
        if (it + 1 < NIT) {
            loadstage(it + 1, st ^ 1);
            asm volatile("cp.async.wait_group 1;\n" ::);
        } else {
            asm volatile("cp.async.wait_group 0;\n" ::);
        }
        __syncthreads();

#pragma unroll
        for (int ks = 0; ks < 2; ks++) {
            int kk = ks * 16;
            int lr = lane & 15;
            int lc = (lane >> 4) * 8;

            uint32_t ah[4][4], al[4][4];
#pragma unroll
            for (int mt = 0; mt < 4; mt++) {
                int roff = (wr * 64 + mt * 16 + lr) * AS_STRIDE + kk + lc;
                uint32_t addr = smem_u32(As + (st * 2 + 0) * AS_TILE + roff);
                asm volatile("ldmatrix.sync.aligned.m8n8.x4.shared.b16 {%0,%1,%2,%3},[%4];"
                             : "=r"(ah[mt][0]), "=r"(ah[mt][1]),
                               "=r"(ah[mt][2]), "=r"(ah[mt][3]) : "r"(addr));
                addr = smem_u32(As + (st * 2 + 1) * AS_TILE + roff);
                asm volatile("ldmatrix.sync.aligned.m8n8.x4.shared.b16 {%0,%1,%2,%3},[%4];"
                             : "=r"(al[mt][0]), "=r"(al[mt][1]),
                               "=r"(al[mt][2]), "=r"(al[mt][3]) : "r"(addr));
            }
            uint32_t bh[4][2], bl[4][2];
#pragma unroll
            for (int np = 0; np < 2; np++) {
                int krow = kk + (lane & 7) + ((lane >> 3) & 1) * 8;
                int col  = wc * 32 + np * 16 + ((lane >> 4) & 1) * 8;
                int boff = krow * BS_STRIDE + col;
                uint32_t addr = smem_u32(Bs + (st * 2 + 0) * BS_TILE + boff);
                uint32_t r0, r1, r2, r3;
                asm volatile("ldmatrix.sync.aligned.m8n8.x4.trans.shared.b16 {%0,%1,%2,%3},[%4];"
                             : "=r"(r0), "=r"(r1), "=r"(r2), "=r"(r3) : "r"(addr));
                bh[np * 2][0] = r0; bh[np * 2][1] = r1;
                bh[np * 2 + 1][0] = r2; bh[np * 2 + 1][1] = r3;
                addr = smem_u32(Bs + (st * 2 + 1) * BS_TILE + boff);
                asm volatile("ldmatrix.sync.aligned.m8n8.x4.trans.shared.b16 {%0,%1,%2,%3},[%4];"
                             : "=r"(r0), "=r"(r1), "=r"(r2), "=r"(r3) : "r"(addr));
                bl[np * 2][0] = r0; bl[np * 2][1] = r1;
                bl[np * 2 + 1][0] = r2; bl[np * 2 + 1][1] = r3;
            }
#pragma unroll
            for (int mt = 0; mt < 4; mt++)
#pragma unroll
                for (int nt = 0; nt < 4; nt++) {
                    mma_16816(acc[mt][nt], ah[mt], bh[nt]);
                    mma_16816(acc[mt][nt], al[mt], bh[nt]);
                    mma_16816(acc[mt][nt], ah[mt], bl[nt]);
                }
        }
        __syncthreads();
    }

    // epilogue
    int g  = lane >> 2;
    int tq = lane & 3;
#pragma unroll
    for (int mt = 0; mt < 4; mt++) {
#pragma unroll
        for (int nt = 0; nt < 4; nt++) {
            int row = m0 + wr * 64 + mt * 16 + g;
            int col = n0 + wc * 32 + nt * 8 + tq * 2;
            if (row < M) {
                C[(size_t)row * N + col]     = acc[mt][nt][0];
                C[(size_t)row * N + col + 1] = acc[mt][nt][1];
            }
            if (row + 8 < M) {
                C[(size_t)(row + 8) * N + col]     = acc[mt][nt][2];
                C[(size_t)(row + 8) * N + col + 1] = acc[mt][nt][3];
            }
        }
    }
}

// ------------------------- propagation (gather-CSR) + fused split -----------
// out[i,:] = sum_e w_e*G[src_e,:] + dinv[i]^2*G[i,:] (+bias)(relu)(+res)
// optionally also emits the bf16 hi/lo split of the result (next GEMM input).
template <int CH, bool RELU, bool RES, bool SPLIT>
__global__ void prop_kernel(const float* __restrict__ G,
                            const float* __restrict__ bias,
                            float* __restrict__ out,
                            __nv_bfloat16* __restrict__ hi,
                            __nv_bfloat16* __restrict__ lo) {
    constexpr int V = CH / 128;  // 4 or 2
    __shared__ int   s_src[128];
    __shared__ float s_w[128];

    int i = blockIdx.x;
    int t = threadIdx.x;
    int c = t * V;

    float di = g_dinv[i];
    float sw = di * di;
    float acc[V];
    const float* gi = G + (size_t)i * CH + c;
    if constexpr (V == 4) {
        float4 v = *(const float4*)gi;
        acc[0] = sw * v.x; acc[1] = sw * v.y; acc[2] = sw * v.z; acc[3] = sw * v.w;
    } else {
        float2 v = *(const float2*)gi;
        acc[0] = sw * v.x; acc[1] = sw * v.y;
    }

    int beg = g_rowstart[i];
    int end = g_rowstart[i + 1];
    for (int e0 = beg; e0 < end; e0 += 128) {
        int n = end - e0;
        if (n > 128) n = 128;
        __syncthreads();
        if (t < n) {
            s_src[t] = g_csr_src[e0 + t];
            s_w[t]   = g_csr_w[e0 + t];
        }
        __syncthreads();
        for (int j = 0; j < n; j++) {
            float wv = s_w[j];
            const float* r = G + (size_t)s_src[j] * CH + c;
            if constexpr (V == 4) {
                float4 v = *(const float4*)r;
                acc[0] += wv * v.x; acc[1] += wv * v.y;
                acc[2] += wv * v.z; acc[3] += wv * v.w;
            } else {
                float2 v = *(const float2*)r;
                acc[0] += wv * v.x; acc[1] += wv * v.y;
            }
        }
    }

    float* o = out + (size_t)i * CH + c;
    float res[V];
#pragma unroll
    for (int j = 0; j < V; j++) {
        float v = acc[j] + bias[c + j];
        if (RELU) v = v > 0.f ? v : 0.f;
        if (RES) v += o[j];  // out aliases H: read old value before overwrite
        o[j] = v;
        res[j] = v;
    }
    if constexpr (SPLIT) {
        size_t base = (size_t)i * CH + c;
#pragma unroll
        for (int j = 0; j < V; j += 2) {
            __nv_bfloat16 h0 = __float2bfloat16(res[j]);
            __nv_bfloat16 h1 = __float2bfloat16(res[j + 1]);
            __nv_bfloat162 hp; hp.x = h0; hp.y = h1;
            __nv_bfloat162 lp;
            lp.x = __float2bfloat16(res[j]     - __bfloat162float(h0));
            lp.y = __float2bfloat16(res[j + 1] - __bfloat162float(h1));
            *(__nv_bfloat162*)(hi + base + j) = hp;
            *(__nv_bfloat162*)(lo + base + j) = lp;
        }
    }
}

// ------------------------- driver -------------------------------------------
extern "C" void kernel_launch(void* const* d_in, const int* in_sizes, int n_in,
                              void* d_out, int out_size) {
    (void)in_sizes; (void)n_in; (void)out_size;
    const float* x   = (const float*)d_in[0];
    const void*  ei  = d_in[1];               // int32 or int64, detected on device
    const float* W1  = (const float*)d_in[2];
    const float* b1  = (const float*)d_in[3];
    const float* Wr  = (const float*)d_in[4];
    const float* br  = (const float*)d_in[5];
    const float* Wx  = (const float*)d_in[6];
    const float* bx  = (const float*)d_in[7];
    float*       out = (float*)d_out;

    void* p;
    cudaGetSymbolAddress(&p, g_H);  float* H = (float*)p;
    cudaGetSymbolAddress(&p, g_G);  float* G = (float*)p;
    cudaGetSymbolAddress(&p, g_Ah); __nv_bfloat16* Ah = (__nv_bfloat16*)p;
    cudaGetSymbolAddress(&p, g_Al); __nv_bfloat16* Al = (__nv_bfloat16*)p;
    cudaGetSymbolAddress(&p, g_Wh); __nv_bfloat16* Wh = (__nv_bfloat16*)p;
    cudaGetSymbolAddress(&p, g_Wl); __nv_bfloat16* Wl = (__nv_bfloat16*)p;

    static int smem_set = 0;
    if (!smem_set) {
        cudaFuncSetAttribute(gemm_bf16x3,
                             cudaFuncAttributeMaxDynamicSharedMemorySize, GEMM_SMEM);
        smem_set = 1;
    }

    // graph preprocessing
    detect_kernel<<<1, 32>>>((const int*)ei);
    zero_kernel<<<(N_NODES + 255) / 256, 256>>>();
    deg_kernel<<<(N_EDGES + 255) / 256, 256>>>(ei);
    dinv_kernel<<<(N_NODES + 255) / 256, 256>>>();
    scan_kernel<<<1, 1024>>>();
    scatter_kernel<<<(N_EDGES + 255) / 256, 256>>>(ei);

    // weight splits (tiny)
    split_kernel<<<(WSZ + 255) / 256, 256>>>(W1, Wh + 0 * WSZ, Wl + 0 * WSZ, WSZ);
    split_kernel<<<(WSZ + 255) / 256, 256>>>(Wr, Wh + 1 * WSZ, Wl + 1 * WSZ, WSZ);
    split_kernel<<<(C_HID * C_OUT + 255) / 256, 256>>>(Wx, Wh + 2 * WSZ, Wl + 2 * WSZ,
                                                       C_HID * C_OUT);

    const int NE = N_NODES * C_HID;
    dim3 gg((N_NODES + 127) / 128, C_HID / 128);

    // layer 1: h = relu(P(x@W1) + b1); prop emits bf16 split of H
    split_kernel<<<(NE + 255) / 256, 256>>>(x, Ah, Al, NE);
    gemm_bf16x3<<<gg, 256, GEMM_SMEM>>>(Ah, Al, Wh + 0 * WSZ, Wl + 0 * WSZ, G,
                                        N_NODES, C_HID);
    prop_kernel<512, true, false, true><<<N_NODES, 128>>>(G, b1, H, Ah, Al);

    // 4 shared residual layers: h = relu(P(h@Wr) + br) + h
    for (int d = 0; d < 4; d++) {
        gemm_bf16x3<<<gg, 256, GEMM_SMEM>>>(Ah, Al, Wh + 1 * WSZ, Wl + 1 * WSZ, G,
                                            N_NODES, C_HID);
        prop_kernel<512, true, true, true><<<N_NODES, 128>>>(G, br, H, Ah, Al);
    }

    // output layer: out = P(h@Wx) + bx
    dim3 g2((N_NODES + 127) / 128, C_OUT / 128);
    gemm_bf16x3<<<g2, 256, GEMM_SMEM>>>(Ah, Al, Wh + 2 * WSZ, Wl + 2 * WSZ, G,
                                        N_NODES, C_OUT);
    prop_kernel<256, false, false, false><<<N_NODES, 128>>>(G, bx, out, nullptr, nullptr);
}